// round 2
// baseline (speedup 1.0000x reference)
#include <cuda_runtime.h>
#include <math.h>

#define B 256
#define D 512
#define P 5
#define NCLS 11003
#define SEGC 6
#define HH 4096           // 64*64
#define NPIX (1280*4096)  // B*P*H*H
#define SCALE 28.0f
#define ALPHA 0.6f
#define BETA 0.4f
#define SPC 10.0f
#define SNC 40.0f
#define TOPK 8
#define M_TOT 512         // 256 visual rows + 256 textual rows

// ---------------- scratch (device globals; no allocation) ----------------
__device__ float d_An[M_TOT * D];          // rows 0..255 = vn, 256..511 = tn
__device__ float d_pen[P * B * D];
__device__ float d_aen[P * B * D];
__device__ float d_invw[NCLS + 8];
__device__ float d_rowsum[M_TOT];          // sum exp(logit - 28) per row
__device__ float d_lablogit[M_TOT];
__device__ float d_sim[6 * B * B];         // s=0..4 parts, s=5 global (vn@tn^T)
__device__ int   d_boost1[P * B];
__device__ int   d_boost2[P * B];
__device__ float d_acc[8];                 // 0: mask sum, 1: global sum, 2: local sum

__device__ __forceinline__ float softplusf(float x) {
    return fmaxf(x, 0.f) + log1pf(expf(-fabsf(x)));
}

// ---------------- init: zero accumulators every launch ----------------
__global__ void k_init() {
    int t = threadIdx.x;
    if (t < M_TOT) d_rowsum[t] = 0.f;
    if (t < 8) d_acc[t] = 0.f;
}

// ---------------- normalize all embedding rows ----------------
// 3072 rows of 512 floats: [vn 256][tn 256][pe 1280][ae 1280]; one warp per row
__global__ void k_normalize(const float* __restrict__ vis, const float* __restrict__ txt,
                            const float* __restrict__ pe, const float* __restrict__ ae) {
    int warp = (blockIdx.x * blockDim.x + threadIdx.x) >> 5;
    int lane = threadIdx.x & 31;
    if (warp >= 3072) return;
    const float* src;
    float* dst;
    if (warp < 256)       { src = vis + warp * D;            dst = d_An  + warp * D; }
    else if (warp < 512)  { src = txt + (warp - 256) * D;    dst = d_An  + warp * D; }
    else if (warp < 1792) { src = pe  + (warp - 512) * D;    dst = d_pen + (warp - 512) * D; }
    else                  { src = ae  + (warp - 1792) * D;   dst = d_aen + (warp - 1792) * D; }
    float ss = 0.f;
    for (int d = lane; d < D; d += 32) { float x = src[d]; ss += x * x; }
    #pragma unroll
    for (int o = 16; o > 0; o >>= 1) ss += __shfl_xor_sync(0xffffffff, ss, o);
    float inv = rsqrtf(ss);
    for (int d = lane; d < D; d += 32) dst[d] = src[d] * inv;
}

// ---------------- W column inverse norms ----------------
__global__ void k_invw(const float* __restrict__ W) {
    int c = blockIdx.x * blockDim.x + threadIdx.x;
    if (c >= NCLS) return;
    float ss = 0.f;
    for (int k = 0; k < D; k++) { float x = W[k * NCLS + c]; ss += x * x; }
    d_invw[c] = rsqrtf(ss);
}

// ---------------- main GEMM + fused exp-sum ----------------
// A[512x512] @ W[512x11003]; per tile compute exp(28*dot*invw - 28), reduce per row.
// BM=128, BN=128, BK=16, 256 threads, 8x8 micro-tile.
__global__ void __launch_bounds__(256)
k_gemm_sumexp(const float* __restrict__ W) {
    __shared__ float As[16][128];
    __shared__ float Bs[16][132];
    __shared__ float srow[128];
    const int tx = threadIdx.x & 15;
    const int ty = threadIdx.x >> 4;
    const int n0 = blockIdx.x * 128;
    const int m0 = blockIdx.y * 128;
    float acc[8][8];
    #pragma unroll
    for (int i = 0; i < 8; i++)
        #pragma unroll
        for (int j = 0; j < 8; j++) acc[i][j] = 0.f;

    for (int k0 = 0; k0 < D; k0 += 16) {
        // A tile: 128 rows x 16 cols = 512 float4s; 2 per thread (transposed store)
        #pragma unroll
        for (int i = 0; i < 2; i++) {
            int li = threadIdx.x + i * 256;
            int m = li >> 2;
            int kk = (li & 3) * 4;
            float4 v = *(const float4*)(d_An + (m0 + m) * D + k0 + kk);
            As[kk + 0][m] = v.x; As[kk + 1][m] = v.y;
            As[kk + 2][m] = v.z; As[kk + 3][m] = v.w;
        }
        // B tile: 16 rows x 128 cols scalar (NCLS odd stride -> no float4)
        #pragma unroll
        for (int i = 0; i < 8; i++) {
            int li = threadIdx.x + i * 256;
            int kk = li >> 7;
            int n  = li & 127;
            int gn = n0 + n;
            Bs[kk][n] = (gn < NCLS) ? W[(k0 + kk) * NCLS + gn] : 0.f;
        }
        __syncthreads();
        #pragma unroll
        for (int k = 0; k < 16; k++) {
            float a[8], b[8];
            #pragma unroll
            for (int i = 0; i < 8; i++) a[i] = As[k][ty * 8 + i];
            #pragma unroll
            for (int j = 0; j < 8; j++) b[j] = Bs[k][tx * 8 + j];
            #pragma unroll
            for (int i = 0; i < 8; i++)
                #pragma unroll
                for (int j = 0; j < 8; j++) acc[i][j] = fmaf(a[i], b[j], acc[i][j]);
        }
        __syncthreads();
    }

    // epilogue: logit = 28 * acc * invw[col]; accumulate exp(logit - 28) per row
    if (threadIdx.x < 128) srow[threadIdx.x] = 0.f;
    __syncthreads();
    float iv[8];
    bool valid[8];
    #pragma unroll
    for (int j = 0; j < 8; j++) {
        int gn = n0 + tx * 8 + j;
        valid[j] = (gn < NCLS);
        iv[j] = valid[j] ? d_invw[gn] : 0.f;
    }
    #pragma unroll
    for (int i = 0; i < 8; i++) {
        float rs = 0.f;
        #pragma unroll
        for (int j = 0; j < 8; j++) {
            if (valid[j]) rs += expf(SCALE * acc[i][j] * iv[j] - SCALE);
        }
        atomicAdd(&srow[ty * 8 + i], rs);
    }
    __syncthreads();
    if (threadIdx.x < 128) atomicAdd(&d_rowsum[m0 + threadIdx.x], srow[threadIdx.x]);
}

// ---------------- label logits: one warp per row ----------------
__global__ void k_label_logits(const float* __restrict__ W, const int* __restrict__ labels) {
    int warp = (blockIdx.x * blockDim.x + threadIdx.x) >> 5;
    int lane = threadIdx.x & 31;
    if (warp >= M_TOT) return;
    int lab = labels[warp & 255];
    float ss = 0.f;
    for (int d = lane; d < D; d += 32) ss += d_An[warp * D + d] * W[d * NCLS + lab];
    #pragma unroll
    for (int o = 16; o > 0; o >>= 1) ss += __shfl_xor_sync(0xffffffff, ss, o);
    if (lane == 0) d_lablogit[warp] = SCALE * ss * d_invw[lab];
}

// ---------------- similarity matrices (5 parts + global) ----------------
// sim[s] = A_s @ B_s^T, 256x256xK512. Tile 64x64, BK=32, 256 threads, 4x4 micro.
__global__ void __launch_bounds__(256)
k_sims() {
    const int s = blockIdx.z;
    const float* Ap = (s < 5) ? (d_pen + s * B * D) : d_An;              // vn
    const float* Bp = (s < 5) ? (d_aen + s * B * D) : (d_An + 256 * D);  // tn
    __shared__ float As[32][64];
    __shared__ float Bs[32][68];
    const int tx = threadIdx.x & 15;
    const int ty = threadIdx.x >> 4;
    const int m0 = blockIdx.y * 64;
    const int n0 = blockIdx.x * 64;
    float acc[4][4];
    #pragma unroll
    for (int i = 0; i < 4; i++)
        #pragma unroll
        for (int j = 0; j < 4; j++) acc[i][j] = 0.f;

    for (int k0 = 0; k0 < D; k0 += 32) {
        #pragma unroll
        for (int i = 0; i < 2; i++) {
            int li = threadIdx.x + i * 256;
            int m = li >> 3;
            int kk = (li & 7) * 4;
            float4 va = *(const float4*)(Ap + (m0 + m) * D + k0 + kk);
            As[kk + 0][m] = va.x; As[kk + 1][m] = va.y;
            As[kk + 2][m] = va.z; As[kk + 3][m] = va.w;
            float4 vb = *(const float4*)(Bp + (n0 + m) * D + k0 + kk);
            Bs[kk + 0][m] = vb.x; Bs[kk + 1][m] = vb.y;
            Bs[kk + 2][m] = vb.z; Bs[kk + 3][m] = vb.w;
        }
        __syncthreads();
        #pragma unroll
        for (int k = 0; k < 32; k++) {
            float a[4], b[4];
            #pragma unroll
            for (int i = 0; i < 4; i++) a[i] = As[k][ty * 4 + i];
            #pragma unroll
            for (int j = 0; j < 4; j++) b[j] = Bs[k][tx * 4 + j];
            #pragma unroll
            for (int i = 0; i < 4; i++)
                #pragma unroll
                for (int j = 0; j < 4; j++) acc[i][j] = fmaf(a[i], b[j], acc[i][j]);
        }
        __syncthreads();
    }
    #pragma unroll
    for (int i = 0; i < 4; i++)
        #pragma unroll
        for (int j = 0; j < 4; j++)
            d_sim[s * (B * B) + (m0 + ty * 4 + i) * B + n0 + tx * 4 + j] = acc[i][j];
}

// ---------------- top-8 boost flags (replicates reference's row index = part index) ----------------
__global__ void k_topk() {
    int p = blockIdx.x;          // 0..4
    const float* S = d_sim + p * (B * B);
    __shared__ int f1[8], f2[8];
    for (int c = threadIdx.x; c < B; c += 32) {
        d_boost1[p * B + c] = 0;
        d_boost2[p * B + c] = 0;
    }
    if (threadIdx.x == 0 || threadIdx.x == 1) {
        bool colmode = (threadIdx.x == 1);
        float val[8]; int idx[8];
        #pragma unroll
        for (int t = 0; t < 8; t++) { val[t] = -1e30f; idx[t] = -1; }
        for (int c = 0; c < B; c++) {
            float v = colmode ? S[c * B + p] : S[p * B + c];
            if (v > val[7]) {
                int j = 7;
                while (j > 0 && v > val[j - 1]) { val[j] = val[j - 1]; idx[j] = idx[j - 1]; j--; }
                val[j] = v; idx[j] = c;
            }
        }
        int* f = colmode ? f2 : f1;
        #pragma unroll
        for (int t = 0; t < 8; t++) f[t] = idx[t];
    }
    __syncthreads();
    if (threadIdx.x < 8) {
        // is row p in top-8 of column j?
        int j = f1[threadIdx.x];
        float ref = S[p * B + j];
        int cnt = 0;
        for (int k = 0; k < B; k++) {
            float v = S[k * B + j];
            if (v > ref || (v == ref && k < p)) cnt++;
        }
        if (cnt < TOPK) d_boost1[p * B + j] = 1;
    } else if (threadIdx.x < 16) {
        // is column p in top-8 of row j?
        int j = f2[threadIdx.x - 8];
        float ref = S[j * B + p];
        int cnt = 0;
        for (int k = 0; k < B; k++) {
            float v = S[j * B + k];
            if (v > ref || (v == ref && k < p)) cnt++;
        }
        if (cnt < TOPK) d_boost2[p * B + j] = 1;
    }
}

// ---------------- align losses reduce: one block per (s, row) ----------------
// vmask/tmask arrive as int32 (bool marshaled by the harness)
__global__ void k_align(const int* __restrict__ labels, const int* __restrict__ vmask,
                        const int* __restrict__ tmask) {
    int s = blockIdx.x >> 8;   // 0..5
    int r = blockIdx.x & 255;
    int c = threadIdx.x;       // 256 threads
    float v = d_sim[s * (B * B) + r * B + c];
    bool match = (labels[c] == labels[r]);
    float Lp = softplusf(-SPC * (v - ALPHA));
    float Ln = softplusf( SNC * (v - BETA));
    float contrib;
    if (s == 5) {
        contrib = match ? Lp : Ln;
    } else {
        int p = s;
        bool vr = vmask[r * P + p] != 0;
        bool vc = vmask[c * P + p] != 0, tc = tmask[c * P + p] != 0;
        float t1 = (vr && tc) ? ((match || d_boost1[p * B + c]) ? Lp : Ln) : 0.f;
        float t2 = ((vc && tc) && vr) ? ((match || d_boost2[p * B + r]) ? Lp : Ln) : 0.f;
        contrib = t1 + t2;
    }
    __shared__ float red[256];
    red[c] = contrib;
    __syncthreads();
    #pragma unroll
    for (int o = 128; o > 0; o >>= 1) {
        if (c < o) red[c] += red[c + o];
        __syncthreads();
    }
    if (c == 0) atomicAdd(&d_acc[(s == 5) ? 1 : 2], red[0]);
}

// ---------------- mask loss: softmax CE over 6 channels ----------------
__global__ void k_mask(const float* __restrict__ seg, const int* __restrict__ masks) {
    int i = blockIdx.x * 256 + threadIdx.x;  // pixel id
    float ce = 0.f;
    if (i < NPIX) {
        const float* base = seg + (long long)(i >> 12) * (SEGC * HH) + (i & 4095);
        float x[SEGC];
        #pragma unroll
        for (int ch = 0; ch < SEGC; ch++) x[ch] = base[ch * HH];
        float m = x[0];
        #pragma unroll
        for (int ch = 1; ch < SEGC; ch++) m = fmaxf(m, x[ch]);
        float ssum = 0.f;
        #pragma unroll
        for (int ch = 0; ch < SEGC; ch++) ssum += expf(x[ch] - m);
        int mk = masks[i];
        ce = m + logf(ssum) - x[mk];
    }
    __shared__ float red[256];
    red[threadIdx.x] = ce;
    __syncthreads();
    #pragma unroll
    for (int o = 128; o > 0; o >>= 1) {
        if (threadIdx.x < o) red[threadIdx.x] += red[threadIdx.x + o];
        __syncthreads();
    }
    if (threadIdx.x == 0) atomicAdd(&d_acc[0], red[0]);
}

// ---------------- finalize ----------------
__global__ void k_finalize(float* __restrict__ out) {
    __shared__ float sv[M_TOT];
    int t = threadIdx.x;
    sv[t] = SCALE + logf(d_rowsum[t]) - d_lablogit[t];
    __syncthreads();
    if (t == 0) {
        float svl = 0.f, stl = 0.f;
        for (int i = 0; i < 256; i++) { svl += sv[i]; stl += sv[i + 256]; }
        out[0] = svl / 256.f + stl / 256.f;              // instance loss
        out[1] = (float)P * d_acc[0] / (float)NPIX;      // mask loss
        out[2] = 2.f * d_acc[1] / 256.f;                 // global align
        out[3] = d_acc[2] / (256.f * (float)P);          // local align
    }
}

extern "C" void kernel_launch(void* const* d_in, const int* in_sizes, int n_in,
                              void* d_out, int out_size) {
    const float* vis   = (const float*)d_in[0];
    const float* txt   = (const float*)d_in[1];
    const float* pe    = (const float*)d_in[2];
    const float* ae    = (const float*)d_in[3];
    const float* seg   = (const float*)d_in[4];
    const float* W     = (const float*)d_in[5];
    const int*   labels= (const int*)d_in[6];
    const int*   masks = (const int*)d_in[7];
    const int*   vmask = (const int*)d_in[8];
    const int*   tmask = (const int*)d_in[9];
    float* out = (float*)d_out;

    k_init<<<1, 512>>>();
    k_normalize<<<(3072 * 32 + 255) / 256, 256>>>(vis, txt, pe, ae);
    k_invw<<<(NCLS + 255) / 256, 256>>>(W);
    {
        dim3 grid((NCLS + 127) / 128, M_TOT / 128);
        k_gemm_sumexp<<<grid, 256>>>(W);
    }
    k_label_logits<<<(M_TOT * 32 + 255) / 256, 256>>>(W, labels);
    {
        dim3 grid(B / 64, B / 64, 6);
        k_sims<<<grid, 256>>>();
    }
    k_topk<<<P, 32>>>();
    k_align<<<6 * B, 256>>>(labels, vmask, tmask);
    k_mask<<<(NPIX + 255) / 256, 256>>>(seg, masks);
    k_finalize<<<1, M_TOT>>>(out);
}

// round 4
// speedup vs baseline: 1.3947x; 1.3947x over previous
#include <cuda_runtime.h>
#include <cuda_bf16.h>
#include <cstdint>
#include <math.h>

#define B 256
#define D 512
#define P 5
#define NCLS 11003
#define NPAD 11008        // 86 * 128
#define SEGC 6
#define HH 4096           // 64*64
#define NPIX (1280*4096)  // B*P*H*H
#define SCALE 28.0f
#define ALPHA 0.6f
#define BETA 0.4f
#define SPC 10.0f
#define SNC 40.0f
#define TOPK 8
#define M_TOT 512         // 256 visual rows + 256 textual rows

// ---------------- scratch (device globals; no allocation) ----------------
__device__ float d_An[M_TOT * D];          // rows 0..255 = vn, 256..511 = tn
__device__ __align__(16) __nv_bfloat16 d_Ahi[M_TOT * D];
__device__ __align__(16) __nv_bfloat16 d_Alo[M_TOT * D];
__device__ __align__(16) __nv_bfloat16 d_Wthi[NPAD * D];   // [n][k] transposed, invw-scaled
__device__ __align__(16) __nv_bfloat16 d_Wtlo[NPAD * D];
__device__ float d_pen[P * B * D];
__device__ float d_aen[P * B * D];
__device__ float d_invw[NPAD];
__device__ float d_rowsum[M_TOT];          // sum exp(logit - 28) per row
__device__ float d_lablogit[M_TOT];
__device__ float d_sim[6 * B * B];         // s=0..4 parts, s=5 global (vn@tn^T)
__device__ int   d_boost1[P * B];
__device__ int   d_boost2[P * B];
__device__ float d_acc[8];                 // 0: mask sum, 1: global sum, 2: local sum

__device__ __forceinline__ float softplusf(float x) {
    return fmaxf(x, 0.f) + log1pf(expf(-fabsf(x)));
}

__device__ __forceinline__ uint32_t smem_u32(const void* p) {
    uint32_t a;
    asm("{ .reg .u64 t; cvta.to.shared.u64 t, %1; cvt.u32.u64 %0, t; }" : "=r"(a) : "l"(p));
    return a;
}
__device__ __forceinline__ void cp16(uint32_t s, const void* g) {
    asm volatile("cp.async.cg.shared.global [%0], [%1], 16;" :: "r"(s), "l"(g));
}
#define CP_COMMIT() asm volatile("cp.async.commit_group;" ::: "memory")
#define CP_WAIT(n)  asm volatile("cp.async.wait_group %0;" :: "n"(n) : "memory")

#define LDSM4(r0, r1, r2, r3, addr) \
    asm volatile("ldmatrix.sync.aligned.m8n8.x4.shared.b16 {%0,%1,%2,%3}, [%4];" \
                 : "=r"(r0), "=r"(r1), "=r"(r2), "=r"(r3) : "r"(addr))

#define MMA16816(d, a, b0, b1) \
    asm volatile("mma.sync.aligned.m16n8k16.row.col.f32.bf16.bf16.f32 " \
                 "{%0,%1,%2,%3},{%4,%5,%6,%7},{%8,%9},{%0,%1,%2,%3};" \
                 : "+f"((d)[0]), "+f"((d)[1]), "+f"((d)[2]), "+f"((d)[3]) \
                 : "r"((a)[0]), "r"((a)[1]), "r"((a)[2]), "r"((a)[3]), "r"(b0), "r"(b1))

// ---------------- init: zero accumulators every launch ----------------
__global__ void k_init() {
    int t = threadIdx.x;
    if (t < M_TOT) d_rowsum[t] = 0.f;
    if (t < 8) d_acc[t] = 0.f;
}

// ---------------- normalize all embedding rows (+ bf16 hi/lo for An) ----------------
__global__ void k_normalize(const float* __restrict__ vis, const float* __restrict__ txt,
                            const float* __restrict__ pe, const float* __restrict__ ae) {
    int warp = (blockIdx.x * blockDim.x + threadIdx.x) >> 5;
    int lane = threadIdx.x & 31;
    if (warp >= 3072) return;
    const float* src;
    float* dst;
    if (warp < 256)       { src = vis + warp * D;            dst = d_An  + warp * D; }
    else if (warp < 512)  { src = txt + (warp - 256) * D;    dst = d_An  + warp * D; }
    else if (warp < 1792) { src = pe  + (warp - 512) * D;    dst = d_pen + (warp - 512) * D; }
    else                  { src = ae  + (warp - 1792) * D;   dst = d_aen + (warp - 1792) * D; }
    float ss = 0.f;
    for (int d = lane; d < D; d += 32) { float x = src[d]; ss += x * x; }
    #pragma unroll
    for (int o = 16; o > 0; o >>= 1) ss += __shfl_xor_sync(0xffffffff, ss, o);
    float inv = rsqrtf(ss);
    if (warp < 512) {
        for (int d = lane; d < D; d += 32) {
            float x = src[d] * inv;
            dst[d] = x;
            __nv_bfloat16 h = __float2bfloat16(x);
            d_Ahi[warp * D + d] = h;
            d_Alo[warp * D + d] = __float2bfloat16(x - __bfloat162float(h));
        }
    } else {
        for (int d = lane; d < D; d += 32) dst[d] = src[d] * inv;
    }
}

// ---------------- W column inverse norms ----------------
__global__ void k_invw(const float* __restrict__ W) {
    __shared__ float red[4][128];
    int t = threadIdx.x;
    int c = t & 127;
    int ks = t >> 7;                 // 0..3
    int n = blockIdx.x * 128 + c;
    float ss = 0.f;
    if (n < NCLS) {
        for (int k = ks * 128; k < ks * 128 + 128; k++) {
            float x = W[k * NCLS + n];
            ss += x * x;
        }
    }
    red[ks][c] = ss;
    __syncthreads();
    if (t < 128) {
        float s = red[0][c] + red[1][c] + red[2][c] + red[3][c];
        d_invw[n] = (n < NCLS) ? rsqrtf(s) : 0.f;
    }
}

// ---------------- W -> bf16 hi/lo transpose + invw scale ----------------
__global__ void __launch_bounds__(256)
k_wconv(const float* __restrict__ W) {
    __shared__ float S[64][129];
    __shared__ float sInv[128];
    int t = threadIdx.x;
    int n0 = blockIdx.x * 128;
    int kt = blockIdx.y;             // 0..7, 64 k each
    if (t < 128) sInv[t] = d_invw[n0 + t];
    #pragma unroll
    for (int i = 0; i < 32; i++) {
        int idx = t + (i << 8);
        int kk = idx >> 7;
        int c = idx & 127;
        int n = n0 + c;
        S[kk][c] = (n < NCLS) ? W[(kt * 64 + kk) * NCLS + n] : 0.f;
    }
    __syncthreads();
    #pragma unroll
    for (int i = 0; i < 4; i++) {
        int it = t + (i << 8);
        int row = it >> 3;           // 0..127
        int ch = it & 7;             // 8 bf16 = 16B
        float iv = sInv[row];
        __nv_bfloat16 hi8[8], lo8[8];
        #pragma unroll
        for (int j = 0; j < 8; j++) {
            float x = S[ch * 8 + j][row] * iv;
            __nv_bfloat16 h = __float2bfloat16(x);
            hi8[j] = h;
            lo8[j] = __float2bfloat16(x - __bfloat162float(h));
        }
        long long o = (long long)(n0 + row) * D + kt * 64 + ch * 8;
        *(uint4*)&d_Wthi[o] = *(const uint4*)hi8;
        *(uint4*)&d_Wtlo[o] = *(const uint4*)lo8;
    }
}

// ---------------- bf16 mma.sync GEMM + fused exp-sum ----------------
// 128x128 tile, BK=32, 8 warps (2x4), warp tile 64x32, 3-way hi/lo split.
#define STRIDE 80                         // bytes per 32-k row in smem
#define TILE_B (128 * STRIDE)             // 10240
#define STAGE_B (4 * TILE_B)              // 40960

__global__ void __launch_bounds__(256, 1)
k_mma_sumexp() {
    extern __shared__ char smem[];
    __shared__ float srow[128];
    const uint32_t sbase = smem_u32(smem);
    const int tid = threadIdx.x;
    const int wid = tid >> 5;
    const int lane = tid & 31;
    const int warp_m = wid >> 2;          // 0..1
    const int warp_n = wid & 3;           // 0..3
    const int n0 = blockIdx.x * 128;
    const int m0 = blockIdx.y * 128;

    if (tid < 128) srow[tid] = 0.f;

    // cp.async stage loader: 4 tiles x 128 rows x 2 chunks16B... (4 chunks of 16B per row)
    auto load_stage = [&](int c, int buf) {
        const int k0 = c * 32;
        const __nv_bfloat16* baseA = d_Ahi + m0 * D + k0;
        const __nv_bfloat16* baseAl = d_Alo + m0 * D + k0;
        const __nv_bfloat16* baseB = d_Wthi + (size_t)n0 * D + k0;
        const __nv_bfloat16* baseBl = d_Wtlo + (size_t)n0 * D + k0;
        uint32_t sb = sbase + buf * STAGE_B;
        #pragma unroll
        for (int i = 0; i < 2; i++) {
            int idx = i * 256 + tid;       // 0..511
            int row = idx >> 2;
            int ch = idx & 3;
            uint32_t so = row * STRIDE + ch * 16;
            size_t go = (size_t)row * D + ch * 8;
            cp16(sb + 0 * TILE_B + so, baseA + go);
            cp16(sb + 1 * TILE_B + so, baseAl + go);
            cp16(sb + 2 * TILE_B + so, baseB + go);
            cp16(sb + 3 * TILE_B + so, baseBl + go);
        }
    };

    float acc[4][4][4];
    #pragma unroll
    for (int i = 0; i < 4; i++)
        #pragma unroll
        for (int j = 0; j < 4; j++)
            #pragma unroll
            for (int q = 0; q < 4; q++) acc[i][j][q] = 0.f;

    load_stage(0, 0);
    CP_COMMIT();

    const int grp = lane >> 3;            // 0..3
    const int rr = lane & 7;

    for (int c = 0; c < 16; c++) {
        if (c + 1 < 16) { load_stage(c + 1, (c + 1) & 1); CP_COMMIT(); CP_WAIT(1); }
        else            { CP_WAIT(0); }
        __syncthreads();
        uint32_t sb = sbase + (c & 1) * STAGE_B;
        uint32_t stAhi = sb;
        uint32_t stAlo = sb + TILE_B;
        uint32_t stBhi = sb + 2 * TILE_B;
        uint32_t stBlo = sb + 3 * TILE_B;
        #pragma unroll
        for (int k16 = 0; k16 < 2; k16++) {
            uint32_t ahi[4][4], alo[4][4], bhi[2][4], blo[2][4];
            #pragma unroll
            for (int mt = 0; mt < 4; mt++) {
                uint32_t rowa = warp_m * 64 + mt * 16 + ((grp & 1) << 3) + rr;
                uint32_t cha = (k16 << 1) + (grp >> 1);
                uint32_t off = rowa * STRIDE + cha * 16;
                LDSM4(ahi[mt][0], ahi[mt][1], ahi[mt][2], ahi[mt][3], stAhi + off);
                LDSM4(alo[mt][0], alo[mt][1], alo[mt][2], alo[mt][3], stAlo + off);
            }
            #pragma unroll
            for (int np = 0; np < 2; np++) {
                uint32_t rowb = warp_n * 32 + np * 16 + ((grp >> 1) << 3) + rr;
                uint32_t chb = (k16 << 1) + (grp & 1);
                uint32_t off = rowb * STRIDE + chb * 16;
                LDSM4(bhi[np][0], bhi[np][1], bhi[np][2], bhi[np][3], stBhi + off);
                LDSM4(blo[np][0], blo[np][1], blo[np][2], blo[np][3], stBlo + off);
            }
            #pragma unroll
            for (int mt = 0; mt < 4; mt++) {
                #pragma unroll
                for (int nt = 0; nt < 4; nt++) {
                    int pair = nt >> 1, lh = (nt & 1) << 1;
                    MMA16816(acc[mt][nt], ahi[mt], bhi[pair][lh], bhi[pair][lh + 1]);
                    MMA16816(acc[mt][nt], ahi[mt], blo[pair][lh], blo[pair][lh + 1]);
                    MMA16816(acc[mt][nt], alo[mt], bhi[pair][lh], bhi[pair][lh + 1]);
                }
            }
        }
        __syncthreads();
    }

    // epilogue: exp(28*acc - 28), masked to n < NCLS, reduce per row
    const int qrow = lane >> 2;           // 0..7
    const int qcol = (lane & 3) << 1;     // 0,2,4,6
    #pragma unroll
    for (int mt = 0; mt < 4; mt++) {
        float s_lo = 0.f, s_hi = 0.f;
        #pragma unroll
        for (int nt = 0; nt < 4; nt++) {
            int n = n0 + warp_n * 32 + nt * 8 + qcol;
            if (n < NCLS)     s_lo += expf(SCALE * acc[mt][nt][0] - SCALE);
            if (n + 1 < NCLS) s_lo += expf(SCALE * acc[mt][nt][1] - SCALE);
            if (n < NCLS)     s_hi += expf(SCALE * acc[mt][nt][2] - SCALE);
            if (n + 1 < NCLS) s_hi += expf(SCALE * acc[mt][nt][3] - SCALE);
        }
        s_lo += __shfl_xor_sync(0xffffffff, s_lo, 1);
        s_lo += __shfl_xor_sync(0xffffffff, s_lo, 2);
        s_hi += __shfl_xor_sync(0xffffffff, s_hi, 1);
        s_hi += __shfl_xor_sync(0xffffffff, s_hi, 2);
        if ((lane & 3) == 0) {
            atomicAdd(&srow[warp_m * 64 + mt * 16 + qrow], s_lo);
            atomicAdd(&srow[warp_m * 64 + mt * 16 + qrow + 8], s_hi);
        }
    }
    __syncthreads();
    if (tid < 128) atomicAdd(&d_rowsum[m0 + tid], srow[tid]);
}

// ---------------- label logits: one warp per row ----------------
__global__ void k_label_logits(const float* __restrict__ W, const int* __restrict__ labels) {
    int warp = (blockIdx.x * blockDim.x + threadIdx.x) >> 5;
    int lane = threadIdx.x & 31;
    if (warp >= M_TOT) return;
    int lab = labels[warp & 255];
    float ss = 0.f;
    for (int d = lane; d < D; d += 32) ss += d_An[warp * D + d] * W[d * NCLS + lab];
    #pragma unroll
    for (int o = 16; o > 0; o >>= 1) ss += __shfl_xor_sync(0xffffffff, ss, o);
    if (lane == 0) d_lablogit[warp] = SCALE * ss * d_invw[lab];
}

// ---------------- similarity matrices (5 parts + global) ----------------
__global__ void __launch_bounds__(256)
k_sims() {
    const int s = blockIdx.z;
    const float* Ap = (s < 5) ? (d_pen + s * B * D) : d_An;              // vn
    const float* Bp = (s < 5) ? (d_aen + s * B * D) : (d_An + 256 * D);  // tn
    __shared__ float As[32][64];
    __shared__ float Bs[32][68];
    const int tx = threadIdx.x & 15;
    const int ty = threadIdx.x >> 4;
    const int m0 = blockIdx.y * 64;
    const int n0 = blockIdx.x * 64;
    float acc[4][4];
    #pragma unroll
    for (int i = 0; i < 4; i++)
        #pragma unroll
        for (int j = 0; j < 4; j++) acc[i][j] = 0.f;

    for (int k0 = 0; k0 < D; k0 += 32) {
        #pragma unroll
        for (int i = 0; i < 2; i++) {
            int li = threadIdx.x + i * 256;
            int m = li >> 3;
            int kk = (li & 7) * 4;
            float4 va = *(const float4*)(Ap + (m0 + m) * D + k0 + kk);
            As[kk + 0][m] = va.x; As[kk + 1][m] = va.y;
            As[kk + 2][m] = va.z; As[kk + 3][m] = va.w;
            float4 vb = *(const float4*)(Bp + (n0 + m) * D + k0 + kk);
            Bs[kk + 0][m] = vb.x; Bs[kk + 1][m] = vb.y;
            Bs[kk + 2][m] = vb.z; Bs[kk + 3][m] = vb.w;
        }
        __syncthreads();
        #pragma unroll
        for (int k = 0; k < 32; k++) {
            float a[4], b[4];
            #pragma unroll
            for (int i = 0; i < 4; i++) a[i] = As[k][ty * 4 + i];
            #pragma unroll
            for (int j = 0; j < 4; j++) b[j] = Bs[k][tx * 4 + j];
            #pragma unroll
            for (int i = 0; i < 4; i++)
                #pragma unroll
                for (int j = 0; j < 4; j++) acc[i][j] = fmaf(a[i], b[j], acc[i][j]);
        }
        __syncthreads();
    }
    #pragma unroll
    for (int i = 0; i < 4; i++)
        #pragma unroll
        for (int j = 0; j < 4; j++)
            d_sim[s * (B * B) + (m0 + ty * 4 + i) * B + n0 + tx * 4 + j] = acc[i][j];
}

// ---------------- top-8 boost flags ----------------
__global__ void k_topk() {
    int p = blockIdx.x;          // 0..4
    const float* S = d_sim + p * (B * B);
    __shared__ int f1[8], f2[8];
    for (int c = threadIdx.x; c < B; c += 32) {
        d_boost1[p * B + c] = 0;
        d_boost2[p * B + c] = 0;
    }
    if (threadIdx.x == 0 || threadIdx.x == 1) {
        bool colmode = (threadIdx.x == 1);
        float val[8]; int idx[8];
        #pragma unroll
        for (int t = 0; t < 8; t++) { val[t] = -1e30f; idx[t] = -1; }
        for (int c = 0; c < B; c++) {
            float v = colmode ? S[c * B + p] : S[p * B + c];
            if (v > val[7]) {
                int j = 7;
                while (j > 0 && v > val[j - 1]) { val[j] = val[j - 1]; idx[j] = idx[j - 1]; j--; }
                val[j] = v; idx[j] = c;
            }
        }
        int* f = colmode ? f2 : f1;
        #pragma unroll
        for (int t = 0; t < 8; t++) f[t] = idx[t];
    }
    __syncthreads();
    if (threadIdx.x < 8) {
        int j = f1[threadIdx.x];
        float ref = S[p * B + j];
        int cnt = 0;
        for (int k = 0; k < B; k++) {
            float v = S[k * B + j];
            if (v > ref || (v == ref && k < p)) cnt++;
        }
        if (cnt < TOPK) d_boost1[p * B + j] = 1;
    } else if (threadIdx.x < 16) {
        int j = f2[threadIdx.x - 8];
        float ref = S[j * B + p];
        int cnt = 0;
        for (int k = 0; k < B; k++) {
            float v = S[j * B + k];
            if (v > ref || (v == ref && k < p)) cnt++;
        }
        if (cnt < TOPK) d_boost2[p * B + j] = 1;
    }
}

// ---------------- align losses reduce ----------------
__global__ void k_align(const int* __restrict__ labels, const int* __restrict__ vmask,
                        const int* __restrict__ tmask) {
    int s = blockIdx.x >> 8;   // 0..5
    int r = blockIdx.x & 255;
    int c = threadIdx.x;       // 256 threads
    float v = d_sim[s * (B * B) + r * B + c];
    bool match = (labels[c] == labels[r]);
    float Lp = softplusf(-SPC * (v - ALPHA));
    float Ln = softplusf( SNC * (v - BETA));
    float contrib;
    if (s == 5) {
        contrib = match ? Lp : Ln;
    } else {
        int p = s;
        bool vr = vmask[r * P + p] != 0;
        bool vc = vmask[c * P + p] != 0, tc = tmask[c * P + p] != 0;
        float t1 = (vr && tc) ? ((match || d_boost1[p * B + c]) ? Lp : Ln) : 0.f;
        float t2 = ((vc && tc) && vr) ? ((match || d_boost2[p * B + r]) ? Lp : Ln) : 0.f;
        contrib = t1 + t2;
    }
    __shared__ float red[256];
    red[c] = contrib;
    __syncthreads();
    #pragma unroll
    for (int o = 128; o > 0; o >>= 1) {
        if (c < o) red[c] += red[c + o];
        __syncthreads();
    }
    if (c == 0) atomicAdd(&d_acc[(s == 5) ? 1 : 2], red[0]);
}

// ---------------- mask loss: softmax CE over 6 channels (4 px / thread) ----------------
__global__ void __launch_bounds__(256)
k_mask(const float* __restrict__ seg, const int* __restrict__ masks) {
    int i0 = (blockIdx.x * 256 + threadIdx.x) * 4;   // NPIX/4 threads exactly
    const float* base = seg + (size_t)(i0 >> 12) * (SEGC * HH) + (i0 & 4095);
    float xs[SEGC][4];
    #pragma unroll
    for (int ch = 0; ch < SEGC; ch++) {
        float4 v = *(const float4*)(base + ch * HH);
        xs[ch][0] = v.x; xs[ch][1] = v.y; xs[ch][2] = v.z; xs[ch][3] = v.w;
    }
    int4 mk = *(const int4*)(masks + i0);
    int mks[4] = {mk.x, mk.y, mk.z, mk.w};
    float ce = 0.f;
    #pragma unroll
    for (int j = 0; j < 4; j++) {
        float m = xs[0][j];
        #pragma unroll
        for (int ch = 1; ch < SEGC; ch++) m = fmaxf(m, xs[ch][j]);
        float ssum = 0.f;
        #pragma unroll
        for (int ch = 0; ch < SEGC; ch++) ssum += expf(xs[ch][j] - m);
        ce += m + logf(ssum) - xs[mks[j]][j];
    }
    __shared__ float red[256];
    red[threadIdx.x] = ce;
    __syncthreads();
    #pragma unroll
    for (int o = 128; o > 0; o >>= 1) {
        if (threadIdx.x < o) red[threadIdx.x] += red[threadIdx.x + o];
        __syncthreads();
    }
    if (threadIdx.x == 0) atomicAdd(&d_acc[0], red[0]);
}

// ---------------- finalize ----------------
__global__ void k_finalize(float* __restrict__ out) {
    __shared__ float sv[M_TOT];
    int t = threadIdx.x;
    sv[t] = SCALE + logf(d_rowsum[t]) - d_lablogit[t];
    __syncthreads();
    if (t == 0) {
        float svl = 0.f, stl = 0.f;
        for (int i = 0; i < 256; i++) { svl += sv[i]; stl += sv[i + 256]; }
        out[0] = svl / 256.f + stl / 256.f;              // instance loss
        out[1] = (float)P * d_acc[0] / (float)NPIX;      // mask loss
        out[2] = 2.f * d_acc[1] / 256.f;                 // global align
        out[3] = d_acc[2] / (256.f * (float)P);          // local align
    }
}

extern "C" void kernel_launch(void* const* d_in, const int* in_sizes, int n_in,
                              void* d_out, int out_size) {
    const float* vis   = (const float*)d_in[0];
    const float* txt   = (const float*)d_in[1];
    const float* pe    = (const float*)d_in[2];
    const float* ae    = (const float*)d_in[3];
    const float* seg   = (const float*)d_in[4];
    const float* W     = (const float*)d_in[5];
    const int*   labels= (const int*)d_in[6];
    const int*   masks = (const int*)d_in[7];
    const int*   vmask = (const int*)d_in[8];
    const int*   tmask = (const int*)d_in[9];
    float* out = (float*)d_out;

    cudaFuncSetAttribute(k_mma_sumexp, cudaFuncAttributeMaxDynamicSharedMemorySize, 2 * STAGE_B);

    k_init<<<1, 512>>>();
    k_normalize<<<(3072 * 32 + 255) / 256, 256>>>(vis, txt, pe, ae);
    k_invw<<<NPAD / 128, 512>>>(W);
    {
        dim3 g(NPAD / 128, 8);
        k_wconv<<<g, 256>>>(W);
    }
    {
        dim3 g(NPAD / 128, M_TOT / 128);
        k_mma_sumexp<<<g, 256, 2 * STAGE_B>>>();
    }
    k_label_logits<<<(M_TOT * 32 + 255) / 256, 256>>>(W, labels);
    {
        dim3 g(B / 64, B / 64, 6);
        k_sims<<<g, 256>>>();
    }
    k_topk<<<P, 32>>>();
    k_align<<<6 * B, 256>>>(labels, vmask, tmask);
    k_mask<<<NPIX / 1024, 256>>>(seg, masks);
    k_finalize<<<1, M_TOT>>>(out);
}

// round 6
// speedup vs baseline: 2.0274x; 1.4536x over previous
#include <cuda_runtime.h>
#include <cuda_fp16.h>
#include <cstdint>
#include <math.h>

#define B 256
#define D 512
#define P 5
#define NCLS 11003
#define NPAD 11008        // 43 * 256
#define SEGC 6
#define HH 4096           // 64*64
#define NPIX (1280*4096)  // B*P*H*H
#define SCALE 28.0f
#define ALPHA 0.6f
#define BETA 0.4f
#define SPC 10.0f
#define SNC 40.0f
#define TOPK 8
#define M_TOT 512         // 256 visual rows + 256 textual rows

// ---------------- scratch (device globals; no allocation) ----------------
__device__ float d_An[M_TOT * D];                  // rows 0..255 = vn, 256..511 = tn
__device__ __align__(16) __half d_Af16[M_TOT * D];
__device__ __align__(16) __half d_Wtf16[NPAD * D]; // [n][k] transposed, invw-scaled
__device__ float d_pen[P * B * D];
__device__ float d_aen[P * B * D];
__device__ float d_invw[NPAD];
__device__ float d_rowsum[M_TOT];
__device__ float d_lablogit[M_TOT];
__device__ float d_sim[6 * B * B];
__device__ int   d_boost1[P * B];
__device__ int   d_boost2[P * B];
__device__ float d_acc[8];                         // 0: mask, 1: global, 2: local

__device__ __forceinline__ float softplusf(float x) {
    return fmaxf(x, 0.f) + log1pf(expf(-fabsf(x)));
}

__device__ __forceinline__ uint32_t smem_u32(const void* p) {
    uint32_t a;
    asm("{ .reg .u64 t; cvta.to.shared.u64 t, %1; cvt.u32.u64 %0, t; }" : "=r"(a) : "l"(p));
    return a;
}
__device__ __forceinline__ void cp16(uint32_t s, const void* g) {
    asm volatile("cp.async.cg.shared.global [%0], [%1], 16;" :: "r"(s), "l"(g));
}
#define CP_COMMIT() asm volatile("cp.async.commit_group;" ::: "memory")
#define CP_WAIT(n)  asm volatile("cp.async.wait_group %0;" :: "n"(n) : "memory")

#define LDSM4(r0, r1, r2, r3, addr) \
    asm volatile("ldmatrix.sync.aligned.m8n8.x4.shared.b16 {%0,%1,%2,%3}, [%4];" \
                 : "=r"(r0), "=r"(r1), "=r"(r2), "=r"(r3) : "r"(addr))

#define MMA16816F(d, a, b0, b1) \
    asm volatile("mma.sync.aligned.m16n8k16.row.col.f32.f16.f16.f32 " \
                 "{%0,%1,%2,%3},{%4,%5,%6,%7},{%8,%9},{%0,%1,%2,%3};" \
                 : "+f"((d)[0]), "+f"((d)[1]), "+f"((d)[2]), "+f"((d)[3]) \
                 : "r"((a)[0]), "r"((a)[1]), "r"((a)[2]), "r"((a)[3]), "r"(b0), "r"(b1))

// ---------------- init ----------------
__global__ void k_init() {
    int t = threadIdx.x;
    if (t < M_TOT) d_rowsum[t] = 0.f;
    if (t < 8) d_acc[t] = 0.f;
}

// ---------------- normalize all embedding rows (+ fp16 for An) ----------------
__global__ void k_normalize(const float* __restrict__ vis, const float* __restrict__ txt,
                            const float* __restrict__ pe, const float* __restrict__ ae) {
    int warp = (blockIdx.x * blockDim.x + threadIdx.x) >> 5;
    int lane = threadIdx.x & 31;
    if (warp >= 3072) return;
    const float* src;
    float* dst;
    if (warp < 256)       { src = vis + warp * D;            dst = d_An  + warp * D; }
    else if (warp < 512)  { src = txt + (warp - 256) * D;    dst = d_An  + warp * D; }
    else if (warp < 1792) { src = pe  + (warp - 512) * D;    dst = d_pen + (warp - 512) * D; }
    else                  { src = ae  + (warp - 1792) * D;   dst = d_aen + (warp - 1792) * D; }
    float ss = 0.f;
    for (int d = lane; d < D; d += 32) { float x = src[d]; ss += x * x; }
    #pragma unroll
    for (int o = 16; o > 0; o >>= 1) ss += __shfl_xor_sync(0xffffffff, ss, o);
    float inv = rsqrtf(ss);
    if (warp < 512) {
        for (int d = lane; d < D; d += 32) {
            float x = src[d] * inv;
            dst[d] = x;
            d_Af16[warp * D + d] = __float2half_rn(x);
        }
    } else {
        for (int d = lane; d < D; d += 32) dst[d] = src[d] * inv;
    }
}

// ---------------- W column inverse norms ----------------
__global__ void k_invw(const float* __restrict__ W) {
    __shared__ float red[4][128];
    int t = threadIdx.x;
    int c = t & 127;
    int ks = t >> 7;
    int n = blockIdx.x * 128 + c;
    float ss = 0.f;
    if (n < NCLS) {
        for (int k = ks * 128; k < ks * 128 + 128; k++) {
            float x = W[k * NCLS + n];
            ss += x * x;
        }
    }
    red[ks][c] = ss;
    __syncthreads();
    if (t < 128) {
        float s = red[0][c] + red[1][c] + red[2][c] + red[3][c];
        d_invw[n] = (n < NCLS) ? rsqrtf(s) : 0.f;
    }
}

// ---------------- W -> fp16 transpose + invw scale ----------------
__global__ void __launch_bounds__(256)
k_wconv(const float* __restrict__ W) {
    __shared__ float S[64][129];
    __shared__ float sInv[128];
    int t = threadIdx.x;
    int n0 = blockIdx.x * 128;
    int kt = blockIdx.y;             // 0..7, 64 k each
    if (t < 128) sInv[t] = d_invw[n0 + t];
    #pragma unroll
    for (int i = 0; i < 32; i++) {
        int idx = t + (i << 8);
        int kk = idx >> 7;
        int c = idx & 127;
        int n = n0 + c;
        S[kk][c] = (n < NCLS) ? W[(kt * 64 + kk) * NCLS + n] : 0.f;
    }
    __syncthreads();
    #pragma unroll
    for (int i = 0; i < 4; i++) {
        int it = t + (i << 8);
        int row = it >> 3;           // 0..127
        int ch = it & 7;             // 8 fp16 = 16B
        float iv = sInv[row];
        __half h8[8];
        #pragma unroll
        for (int j = 0; j < 8; j++)
            h8[j] = __float2half_rn(S[ch * 8 + j][row] * iv);
        long long o = (long long)(n0 + row) * D + kt * 64 + ch * 8;
        *(uint4*)&d_Wtf16[o] = *(const uint4*)h8;
    }
}

// ---------------- fp16 mma.sync GEMM + fused exp-sum ----------------
// BM=128, BN=256, BK=64, 512 threads (16 warps 4x4), warp tile 32x64.
#define STRIDE 144                         // bytes per 64-k fp16 row (128 data + 16 pad)
#define SM_A 0
#define SM_B (128 * STRIDE)                // 18432
#define STAGE (SM_B + 256 * STRIDE)        // 55296

__global__ void __launch_bounds__(512, 1)
k_mma_sumexp() {
    extern __shared__ char smem[];
    __shared__ float srow[128];
    const uint32_t sbase = smem_u32(smem);
    const int tid = threadIdx.x;
    const int wid = tid >> 5;
    const int lane = tid & 31;
    const int warp_m = wid >> 2;          // 0..3 (32 rows)
    const int warp_n = wid & 3;           // 0..3 (64 cols)
    const int n0 = blockIdx.x * 256;
    const int m0 = blockIdx.y * 128;

    if (tid < 128) srow[tid] = 0.f;

    // Each row = 64 fp16 = 128 bytes = 8 x 16B chunks.
    // A: 128 rows x 8 chunks = 1024 cps; B: 256 rows x 8 chunks = 2048 cps.
    auto load_stage = [&](int c, int buf) {
        const int k0 = c * 64;
        uint32_t sb = sbase + buf * STAGE;
        #pragma unroll
        for (int i = 0; i < 2; i++) {
            int idx = i * 512 + tid;
            int row = idx >> 3, ch = idx & 7;
            cp16(sb + SM_A + row * STRIDE + ch * 16,
                 d_Af16 + (size_t)(m0 + row) * D + k0 + ch * 8);
        }
        #pragma unroll
        for (int i = 0; i < 4; i++) {
            int idx = i * 512 + tid;
            int row = idx >> 3, ch = idx & 7;
            cp16(sb + SM_B + row * STRIDE + ch * 16,
                 d_Wtf16 + (size_t)(n0 + row) * D + k0 + ch * 8);
        }
    };

    float acc[2][8][4];
    #pragma unroll
    for (int i = 0; i < 2; i++)
        #pragma unroll
        for (int j = 0; j < 8; j++)
            #pragma unroll
            for (int q = 0; q < 4; q++) acc[i][j][q] = 0.f;

    load_stage(0, 0);
    CP_COMMIT();

    const int grp = lane >> 3;            // 0..3
    const int rr = lane & 7;

    for (int c = 0; c < 8; c++) {
        if (c + 1 < 8) { load_stage(c + 1, (c + 1) & 1); CP_COMMIT(); CP_WAIT(1); }
        else           { CP_WAIT(0); }
        __syncthreads();
        uint32_t sb = sbase + (c & 1) * STAGE;
        #pragma unroll
        for (int k16 = 0; k16 < 4; k16++) {
            uint32_t a[2][4], b[4][4];
            #pragma unroll
            for (int mt = 0; mt < 2; mt++) {
                uint32_t rowa = warp_m * 32 + mt * 16 + ((grp & 1) << 3) + rr;
                uint32_t cha = (k16 << 1) + (grp >> 1);
                LDSM4(a[mt][0], a[mt][1], a[mt][2], a[mt][3],
                      sb + SM_A + rowa * STRIDE + cha * 16);
            }
            #pragma unroll
            for (int np = 0; np < 4; np++) {
                uint32_t rowb = warp_n * 64 + np * 16 + ((grp >> 1) << 3) + rr;
                uint32_t chb = (k16 << 1) + (grp & 1);
                LDSM4(b[np][0], b[np][1], b[np][2], b[np][3],
                      sb + SM_B + rowb * STRIDE + chb * 16);
            }
            #pragma unroll
            for (int mt = 0; mt < 2; mt++) {
                #pragma unroll
                for (int nt = 0; nt < 8; nt++) {
                    int pair = nt >> 1, lh = (nt & 1) << 1;
                    MMA16816F(acc[mt][nt], a[mt], b[pair][lh], b[pair][lh + 1]);
                }
            }
        }
        __syncthreads();
    }

    // epilogue: exp(28*acc - 28), masked to n < NCLS, reduce per row
    const int qrow = lane >> 2;
    const int qcol = (lane & 3) << 1;
    #pragma unroll
    for (int mt = 0; mt < 2; mt++) {
        float s_lo = 0.f, s_hi = 0.f;
        #pragma unroll
        for (int nt = 0; nt < 8; nt++) {
            int n = n0 + warp_n * 64 + nt * 8 + qcol;
            if (n < NCLS)     { s_lo += expf(SCALE * acc[mt][nt][0] - SCALE);
                                s_hi += expf(SCALE * acc[mt][nt][2] - SCALE); }
            if (n + 1 < NCLS) { s_lo += expf(SCALE * acc[mt][nt][1] - SCALE);
                                s_hi += expf(SCALE * acc[mt][nt][3] - SCALE); }
        }
        s_lo += __shfl_xor_sync(0xffffffff, s_lo, 1);
        s_lo += __shfl_xor_sync(0xffffffff, s_lo, 2);
        s_hi += __shfl_xor_sync(0xffffffff, s_hi, 1);
        s_hi += __shfl_xor_sync(0xffffffff, s_hi, 2);
        if ((lane & 3) == 0) {
            atomicAdd(&srow[warp_m * 32 + mt * 16 + qrow], s_lo);
            atomicAdd(&srow[warp_m * 32 + mt * 16 + qrow + 8], s_hi);
        }
    }
    __syncthreads();
    if (tid < 128) atomicAdd(&d_rowsum[m0 + tid], srow[tid]);
}

// ---------------- label logits: one warp per row (exact fp32) ----------------
__global__ void k_label_logits(const float* __restrict__ W, const int* __restrict__ labels) {
    int warp = (blockIdx.x * blockDim.x + threadIdx.x) >> 5;
    int lane = threadIdx.x & 31;
    if (warp >= M_TOT) return;
    int lab = labels[warp & 255];
    float ss = 0.f;
    for (int d = lane; d < D; d += 32) ss += d_An[warp * D + d] * W[d * NCLS + lab];
    #pragma unroll
    for (int o = 16; o > 0; o >>= 1) ss += __shfl_xor_sync(0xffffffff, ss, o);
    if (lane == 0) d_lablogit[warp] = SCALE * ss * d_invw[lab];
}

// ---------------- similarity matrices (5 parts + global), fp32 ----------------
__global__ void __launch_bounds__(256)
k_sims() {
    const int s = blockIdx.z;
    const float* Ap = (s < 5) ? (d_pen + s * B * D) : d_An;
    const float* Bp = (s < 5) ? (d_aen + s * B * D) : (d_An + 256 * D);
    __shared__ float As[32][64];
    __shared__ float Bs[32][68];
    const int tx = threadIdx.x & 15;
    const int ty = threadIdx.x >> 4;
    const int m0 = blockIdx.y * 64;
    const int n0 = blockIdx.x * 64;
    float acc[4][4];
    #pragma unroll
    for (int i = 0; i < 4; i++)
        #pragma unroll
        for (int j = 0; j < 4; j++) acc[i][j] = 0.f;

    for (int k0 = 0; k0 < D; k0 += 32) {
        #pragma unroll
        for (int i = 0; i < 2; i++) {
            int li = threadIdx.x + i * 256;
            int m = li >> 3;
            int kk = (li & 7) * 4;
            float4 va = *(const float4*)(Ap + (m0 + m) * D + k0 + kk);
            As[kk + 0][m] = va.x; As[kk + 1][m] = va.y;
            As[kk + 2][m] = va.z; As[kk + 3][m] = va.w;
            float4 vb = *(const float4*)(Bp + (n0 + m) * D + k0 + kk);
            Bs[kk + 0][m] = vb.x; Bs[kk + 1][m] = vb.y;
            Bs[kk + 2][m] = vb.z; Bs[kk + 3][m] = vb.w;
        }
        __syncthreads();
        #pragma unroll
        for (int k = 0; k < 32; k++) {
            float a[4], b[4];
            #pragma unroll
            for (int i = 0; i < 4; i++) a[i] = As[k][ty * 4 + i];
            #pragma unroll
            for (int j = 0; j < 4; j++) b[j] = Bs[k][tx * 4 + j];
            #pragma unroll
            for (int i = 0; i < 4; i++)
                #pragma unroll
                for (int j = 0; j < 4; j++) acc[i][j] = fmaf(a[i], b[j], acc[i][j]);
        }
        __syncthreads();
    }
    #pragma unroll
    for (int i = 0; i < 4; i++)
        #pragma unroll
        for (int j = 0; j < 4; j++)
            d_sim[s * (B * B) + (m0 + ty * 4 + i) * B + n0 + tx * 4 + j] = acc[i][j];
}

// ---------------- top-8 boost flags ----------------
__global__ void k_topk() {
    int p = blockIdx.x;
    const float* S = d_sim + p * (B * B);
    __shared__ int f1[8], f2[8];
    for (int c = threadIdx.x; c < B; c += 32) {
        d_boost1[p * B + c] = 0;
        d_boost2[p * B + c] = 0;
    }
    if (threadIdx.x == 0 || threadIdx.x == 1) {
        bool colmode = (threadIdx.x == 1);
        float val[8]; int idx[8];
        #pragma unroll
        for (int t = 0; t < 8; t++) { val[t] = -1e30f; idx[t] = -1; }
        for (int c = 0; c < B; c++) {
            float v = colmode ? S[c * B + p] : S[p * B + c];
            if (v > val[7]) {
                int j = 7;
                while (j > 0 && v > val[j - 1]) { val[j] = val[j - 1]; idx[j] = idx[j - 1]; j--; }
                val[j] = v; idx[j] = c;
            }
        }
        int* f = colmode ? f2 : f1;
        #pragma unroll
        for (int t = 0; t < 8; t++) f[t] = idx[t];
    }
    __syncthreads();
    if (threadIdx.x < 8) {
        int j = f1[threadIdx.x];
        float ref = S[p * B + j];
        int cnt = 0;
        for (int k = 0; k < B; k++) {
            float v = S[k * B + j];
            if (v > ref || (v == ref && k < p)) cnt++;
        }
        if (cnt < TOPK) d_boost1[p * B + j] = 1;
    } else if (threadIdx.x < 16) {
        int j = f2[threadIdx.x - 8];
        float ref = S[j * B + p];
        int cnt = 0;
        for (int k = 0; k < B; k++) {
            float v = S[j * B + k];
            if (v > ref || (v == ref && k < p)) cnt++;
        }
        if (cnt < TOPK) d_boost2[p * B + j] = 1;
    }
}

// ---------------- align losses reduce ----------------
__global__ void k_align(const int* __restrict__ labels, const int* __restrict__ vmask,
                        const int* __restrict__ tmask) {
    int s = blockIdx.x >> 8;
    int r = blockIdx.x & 255;
    int c = threadIdx.x;
    float v = d_sim[s * (B * B) + r * B + c];
    bool match = (labels[c] == labels[r]);
    float Lp = softplusf(-SPC * (v - ALPHA));
    float Ln = softplusf( SNC * (v - BETA));
    float contrib;
    if (s == 5) {
        contrib = match ? Lp : Ln;
    } else {
        int p = s;
        bool vr = vmask[r * P + p] != 0;
        bool vc = vmask[c * P + p] != 0, tc = tmask[c * P + p] != 0;
        float t1 = (vr && tc) ? ((match || d_boost1[p * B + c]) ? Lp : Ln) : 0.f;
        float t2 = ((vc && tc) && vr) ? ((match || d_boost2[p * B + r]) ? Lp : Ln) : 0.f;
        contrib = t1 + t2;
    }
    __shared__ float red[256];
    red[c] = contrib;
    __syncthreads();
    #pragma unroll
    for (int o = 128; o > 0; o >>= 1) {
        if (c < o) red[c] += red[c + o];
        __syncthreads();
    }
    if (c == 0) atomicAdd(&d_acc[(s == 5) ? 1 : 2], red[0]);
}

// ---------------- mask loss: softmax CE over 6 channels (4 px / thread) ----------------
__global__ void __launch_bounds__(256)
k_mask(const float* __restrict__ seg, const int* __restrict__ masks) {
    int i0 = (blockIdx.x * 256 + threadIdx.x) * 4;
    const float* base = seg + (size_t)(i0 >> 12) * (SEGC * HH) + (i0 & 4095);
    float xs[SEGC][4];
    #pragma unroll
    for (int ch = 0; ch < SEGC; ch++) {
        float4 v = *(const float4*)(base + ch * HH);
        xs[ch][0] = v.x; xs[ch][1] = v.y; xs[ch][2] = v.z; xs[ch][3] = v.w;
    }
    int4 mk = *(const int4*)(masks + i0);
    int mks[4] = {mk.x, mk.y, mk.z, mk.w};
    float ce = 0.f;
    #pragma unroll
    for (int j = 0; j < 4; j++) {
        float m = xs[0][j];
        #pragma unroll
        for (int ch = 1; ch < SEGC; ch++) m = fmaxf(m, xs[ch][j]);
        float ssum = 0.f;
        #pragma unroll
        for (int ch = 0; ch < SEGC; ch++) ssum += expf(xs[ch][j] - m);
        ce += m + logf(ssum) - xs[mks[j]][j];
    }
    __shared__ float red[256];
    red[threadIdx.x] = ce;
    __syncthreads();
    #pragma unroll
    for (int o = 128; o > 0; o >>= 1) {
        if (threadIdx.x < o) red[threadIdx.x] += red[threadIdx.x + o];
        __syncthreads();
    }
    if (threadIdx.x == 0) atomicAdd(&d_acc[0], red[0]);
}

// ---------------- finalize ----------------
__global__ void k_finalize(float* __restrict__ out) {
    __shared__ float sv[M_TOT];
    int t = threadIdx.x;
    sv[t] = SCALE + logf(d_rowsum[t]) - d_lablogit[t];
    __syncthreads();
    if (t == 0) {
        float svl = 0.f, stl = 0.f;
        for (int i = 0; i < 256; i++) { svl += sv[i]; stl += sv[i + 256]; }
        out[0] = svl / 256.f + stl / 256.f;
        out[1] = (float)P * d_acc[0] / (float)NPIX;
        out[2] = 2.f * d_acc[1] / 256.f;
        out[3] = d_acc[2] / (256.f * (float)P);
    }
}

extern "C" void kernel_launch(void* const* d_in, const int* in_sizes, int n_in,
                              void* d_out, int out_size) {
    const float* vis   = (const float*)d_in[0];
    const float* txt   = (const float*)d_in[1];
    const float* pe    = (const float*)d_in[2];
    const float* ae    = (const float*)d_in[3];
    const float* seg   = (const float*)d_in[4];
    const float* W     = (const float*)d_in[5];
    const int*   labels= (const int*)d_in[6];
    const int*   masks = (const int*)d_in[7];
    const int*   vmask = (const int*)d_in[8];
    const int*   tmask = (const int*)d_in[9];
    float* out = (float*)d_out;

    static cudaStream_t s1 = nullptr, s2 = nullptr;
    static cudaEvent_t ef1, ef2, ej1, ej2;
    if (!s1) {
        cudaStreamCreateWithFlags(&s1, cudaStreamNonBlocking);
        cudaStreamCreateWithFlags(&s2, cudaStreamNonBlocking);
        cudaEventCreateWithFlags(&ef1, cudaEventDisableTiming);
        cudaEventCreateWithFlags(&ef2, cudaEventDisableTiming);
        cudaEventCreateWithFlags(&ej1, cudaEventDisableTiming);
        cudaEventCreateWithFlags(&ej2, cudaEventDisableTiming);
        cudaFuncSetAttribute(k_mma_sumexp, cudaFuncAttributeMaxDynamicSharedMemorySize, 2 * STAGE);
    }

    k_init<<<1, 512>>>();

    // fork: mask loss (independent of everything except d_acc init)
    cudaEventRecord(ef1, 0);
    cudaStreamWaitEvent(s1, ef1, 0);
    k_mask<<<NPIX / 1024, 256, 0, s1>>>(seg, masks);
    cudaEventRecord(ej1, s1);

    k_normalize<<<(3072 * 32 + 255) / 256, 256>>>(vis, txt, pe, ae);

    // fork: sims -> topk -> align (needs normalize only)
    cudaEventRecord(ef2, 0);
    cudaStreamWaitEvent(s2, ef2, 0);
    {
        dim3 g(B / 64, B / 64, 6);
        k_sims<<<g, 256, 0, s2>>>();
    }
    k_topk<<<P, 32, 0, s2>>>();
    k_align<<<6 * B, 256, 0, s2>>>(labels, vmask, tmask);
    cudaEventRecord(ej2, s2);

    // main chain: instance loss
    k_invw<<<NPAD / 128, 512>>>(W);
    {
        dim3 g(NPAD / 128, 8);
        k_wconv<<<g, 256>>>(W);
    }
    {
        dim3 g(NPAD / 256, M_TOT / 128);
        k_mma_sumexp<<<g, 512, 2 * STAGE>>>();
    }
    k_label_logits<<<(M_TOT * 32 + 255) / 256, 256>>>(W, labels);

    // join
    cudaStreamWaitEvent(0, ej1, 0);
    cudaStreamWaitEvent(0, ej2, 0);
    k_finalize<<<1, M_TOT>>>(out);
}